// round 17
// baseline (speedup 1.0000x reference)
#include <cuda_runtime.h>
#include <cuda_fp16.h>
#include <cstdint>

// ---------------------------------------------------------------------------
// Problem constants
// ---------------------------------------------------------------------------
constexpr int N_NODES = 50000;
constexpr int K_NBR   = 32;
constexpr int F_IN    = 64;
constexpr int F_OUT   = 64;
constexpr int BM      = 128;
constexpr int NBLK    = (N_NODES + BM - 1) / BM;   // 391

// Warp-private A tile: 16 rows x 144 B (72 fp16, padded) = 2304 B per buffer.
constexpr int RSB     = 144;
constexpr int AW_TILE = 16 * RSB;                  // 2304
constexpr int B_TILE  = F_IN * RSB;                // frag kernel only

// Dynamic smem: [warp][buf] A tiles, then per-warp inv + nbr tables (stride 33)
constexpr int SM_INV  = 8 * 2 * AW_TILE;           // 36864
constexpr int SM_NBR  = SM_INV + 8 * 16 * 33 * 4;  // 53760
constexpr int SMEM_BYTES = SM_NBR + 8 * 16 * 33 * 4;   // 70656

// ---------------------------------------------------------------------------
// Device scratch
// ---------------------------------------------------------------------------
__device__ uint4 g_Hh4[(size_t)N_NODES * F_IN * 2 / 16];     // h as fp16, 6.4 MB
// B fragments in mma layout: [k][band][kc][g2][lane] -> uint4 (b0..b3)
__device__ uint4 g_Bfrag[K_NBR * 2 * 4 * 2 * 32];            // 256 KB

// ---------------------------------------------------------------------------
// PTX helpers (baseline PTX — valid at virtual target sm_103)
// ---------------------------------------------------------------------------
__device__ __forceinline__ uint32_t smem_u32(const void* p) {
    uint32_t a;
    asm("{ .reg .u64 t; cvta.to.shared.u64 t, %1; cvt.u32.u64 %0, t; }"
        : "=r"(a) : "l"(p));
    return a;
}
#define LDM_X4(r, addr) \
    asm volatile("ldmatrix.sync.aligned.m8n8.x4.shared.b16 {%0,%1,%2,%3}, [%4];" \
        : "=r"((r)[0]), "=r"((r)[1]), "=r"((r)[2]), "=r"((r)[3]) : "r"(addr))
#define LDM_X4T(r, addr) \
    asm volatile("ldmatrix.sync.aligned.m8n8.x4.trans.shared.b16 {%0,%1,%2,%3}, [%4];" \
        : "=r"((r)[0]), "=r"((r)[1]), "=r"((r)[2]), "=r"((r)[3]) : "r"(addr))
#define MMA16816(d, a, b0, b1) \
    asm volatile("mma.sync.aligned.m16n8k16.row.col.f32.f16.f16.f32 " \
        "{%0,%1,%2,%3}, {%4,%5,%6,%7}, {%8,%9}, {%0,%1,%2,%3};" \
        : "+f"((d)[0]), "+f"((d)[1]), "+f"((d)[2]), "+f"((d)[3]) \
        : "r"((a)[0]), "r"((a)[1]), "r"((a)[2]), "r"((a)[3]), "r"(b0), "r"(b1))

// ---------------------------------------------------------------------------
// Kernel 1: h -> fp16 (2 independent loads per thread for MLP)
// ---------------------------------------------------------------------------
__global__ __launch_bounds__(256) void convert_h_kernel(const float* __restrict__ h)
{
    int i = blockIdx.x * blockDim.x + threadIdx.x;
    constexpr int HALF = N_NODES * F_IN / 8;   // 400000 float4 per half
    if (i >= HALF) return;
    float4 v0 = ((const float4*)h)[i];
    float4 v1 = ((const float4*)h)[i + HALF];
    __half2 a0 = __floats2half2_rn(v0.x, v0.y);
    __half2 b0 = __floats2half2_rn(v0.z, v0.w);
    __half2 a1 = __floats2half2_rn(v1.x, v1.y);
    __half2 b1 = __floats2half2_rn(v1.z, v1.w);
    ((uint2*)g_Hh4)[i]        = make_uint2(*(uint32_t*)&a0, *(uint32_t*)&b0);
    ((uint2*)g_Hh4)[i + HALF] = make_uint2(*(uint32_t*)&a1, *(uint32_t*)&b1);
}

// ---------------------------------------------------------------------------
// Kernel 2: build B fragments (proven in R15). One CTA per neighbor k.
// ---------------------------------------------------------------------------
__global__ __launch_bounds__(256) void frag_w_kernel(const float* __restrict__ W)
{
    __shared__ __align__(16) uint8_t btile[B_TILE];
    const int k   = blockIdx.x;
    const int tid = threadIdx.x;
    const int wid = tid >> 5;
    const int lid = tid & 31;

    {
        const int kk = tid >> 2;
        const int n0 = (tid & 3) * 16;
        const float* src = W + (((size_t)k * F_IN + kk) * F_OUT + n0);
        uint32_t w[8];
#pragma unroll
        for (int j = 0; j < 4; ++j) {
            float4 v = *(const float4*)(src + j * 4);
            __half2 a = __floats2half2_rn(v.x, v.y);
            __half2 b = __floats2half2_rn(v.z, v.w);
            w[2 * j + 0] = *(uint32_t*)&a;
            w[2 * j + 1] = *(uint32_t*)&b;
        }
        uint8_t* dst = btile + kk * RSB + n0 * 2;
        *(uint4*)(dst)      = ((uint4*)w)[0];
        *(uint4*)(dst + 16) = ((uint4*)w)[1];
    }
    __syncthreads();

    const int band = wid & 1;
    const int kc   = wid >> 1;
    const uint32_t sb = smem_u32(btile);
    const uint32_t lrow = (lid & 15);
    const uint32_t loff = (lid >> 4) * 16;
    const uint32_t baseAddr = sb + lrow * RSB + band * 64 + loff + kc * 16 * RSB;
#pragma unroll
    for (int g2 = 0; g2 < 2; ++g2) {
        uint32_t b[4];
        LDM_X4T(b, baseAddr + g2 * 32);
        g_Bfrag[((((size_t)k * 2 + band) * 4 + kc) * 2 + g2) * 32 + lid] =
            make_uint4(b[0], b[1], b[2], b[3]);
    }
}

// ---------------------------------------------------------------------------
// Kernel 3: barrier-free fused gather-scale-GEMM.
// 8 warps; warp w privately owns rows [w*16, w*16+16) x all 64 cols.
// A tile, inv table and nbr table are warp-private smem -> only __syncwarp
// in the loop. B comes from global fragments (L2). Warps drift freely.
// ---------------------------------------------------------------------------
extern __shared__ uint8_t dynsmem[];

__global__ __launch_bounds__(256, 3) void gnn_mma_kernel(
    const int* __restrict__ nidx, const float* __restrict__ pos,
    const float* __restrict__ bias, float* __restrict__ out)
{
    const int tid = threadIdx.x;
    const int wid = tid >> 5;
    const int lid = tid & 31;
    const int node0 = blockIdx.x * BM;

    const uint32_t sbase = smem_u32(dynsmem);
    const uint32_t AW    = sbase + wid * 2 * AW_TILE;        // [buf] stride AW_TILE
    float* invW = (float*)(dynsmem + SM_INV) + wid * 16 * 33;
    int*   nbrW = (int*)  (dynsmem + SM_NBR) + wid * 16 * 33;

    // ---- prologue: per-warp inv + nbr tables ----
    // lane l handles row (l&15), k in [(l>>4)*16, +16)
    {
        const int irow  = lid & 15;
        const int k0    = (lid >> 4) * 16;
        const int igrow = node0 + wid * 16 + irow;
        const bool iok  = (igrow < N_NODES);
        float pix = 0.f, piy = 0.f, piz = 0.f;
        const int* nr = nidx + (size_t)igrow * K_NBR;
        if (iok) {
            pix = pos[(size_t)igrow * 3 + 0];
            piy = pos[(size_t)igrow * 3 + 1];
            piz = pos[(size_t)igrow * 3 + 2];
        }
#pragma unroll 4
        for (int j = 0; j < 16; ++j) {
            int k = k0 + j;
            int   nbr = 0;
            float inv = 0.0f;
            if (iok) {
                nbr = nr[k];
                float dx = pix - pos[(size_t)nbr * 3 + 0];
                float dy = piy - pos[(size_t)nbr * 3 + 1];
                float dz = piz - pos[(size_t)nbr * 3 + 2];
                float sq = fmaf(dx, dx, fmaf(dy, dy, dz * dz));
                inv = (sq == 0.0f) ? 2.0f : rsqrtf(sq);   // dist==0 -> 0.5
            }
            invW[irow * 33 + k] = inv;
            nbrW[irow * 33 + k] = nbr;
        }
    }
    __syncwarp();

    // Staging roles within the warp: row rr = lid>>1, half hh = lid&1
    const int rr = lid >> 1;
    const int hh = lid & 1;
    uint8_t* AdstBase = dynsmem + wid * 2 * AW_TILE + rr * RSB + hh * 64;

    auto scale_sts = [&](const uint4* hv, int kn, int buf) {
        __half2 inv2 = __float2half2_rn(invW[rr * 33 + kn]);
        uint8_t* dst = AdstBase + buf * AW_TILE;
#pragma unroll
        for (int j = 0; j < 4; ++j) {
            uint4 v = hv[j];
            __half2* p = (__half2*)&v;
            p[0] = __hmul2(p[0], inv2);
            p[1] = __hmul2(p[1], inv2);
            p[2] = __hmul2(p[2], inv2);
            p[3] = __hmul2(p[3], inv2);
            *(uint4*)(dst + j * 16) = v;
        }
    };

    // ---- prologue: stage k=0 into buf 0 ----
    {
        int nbr0 = nbrW[rr * 33];
        uint4 hv[4];
        const uint4* hs = g_Hh4 + (size_t)nbr0 * 8 + hh * 4;
#pragma unroll
        for (int j = 0; j < 4; ++j) hv[j] = hs[j];
        scale_sts(hv, 0, 0);
    }
    __syncwarp();

    // MMA addressing (warp-private 16-row tile)
    const uint32_t aAddr = AW + (lid & 15) * RSB + (lid >> 4) * 16;

    float acc[8][4];   // n-tile nt = band*4 + g2*2 + half
#pragma unroll
    for (int i = 0; i < 8; ++i)
#pragma unroll
        for (int j = 0; j < 4; ++j) acc[i][j] = 0.0f;

    for (int k = 0; k < K_NBR; ++k) {
        const int buf = k & 1;
        const int kn  = k + 1;

        // prefetch h row (k+1) into regs (consumed after MMA phase)
        uint4 hvn[4];
        if (kn < K_NBR) {
            int nbr_n = nbrW[rr * 33 + kn];
            const uint4* hs = g_Hh4 + (size_t)nbr_n * 8 + hh * 4;
#pragma unroll
            for (int j = 0; j < 4; ++j) hvn[j] = hs[j];
        }

        // MMA(k): A warp-private smem, B fragments from L2
        const uint32_t ab = aAddr + buf * AW_TILE;
        const uint4* bf0 = g_Bfrag + (size_t)k * 512 + lid;
#pragma unroll
        for (int kc = 0; kc < 4; ++kc) {
            uint32_t a[4];
            LDM_X4(a, ab + kc * 32);
#pragma unroll
            for (int band = 0; band < 2; ++band) {
#pragma unroll
                for (int g2 = 0; g2 < 2; ++g2) {
                    uint4 bf = bf0[band * 256 + kc * 64 + g2 * 32];
                    const int nt = band * 4 + g2 * 2;
                    MMA16816(acc[nt + 0], a, bf.x, bf.y);
                    MMA16816(acc[nt + 1], a, bf.z, bf.w);
                }
            }
        }

        if (kn < K_NBR) scale_sts(hvn, kn, buf ^ 1);
        __syncwarp();   // STS (buf^1) visible to next iter's ldmatrix
    }

    // ---- epilogue: bias + leaky_relu(0.01) ----
    const int g  = lid >> 2;
    const int c0 = (lid & 3) * 2;
    const int row0 = node0 + wid * 16 + g;
    const int row1 = row0 + 8;
#pragma unroll
    for (int nt = 0; nt < 8; ++nt) {
        int col = (nt >> 2) * 32 + ((nt >> 1) & 1) * 16 + (nt & 1) * 8 + c0;
        float bx = bias[col], by = bias[col + 1];
        float2 v0 = make_float2(acc[nt][0] + bx, acc[nt][1] + by);
        float2 v1 = make_float2(acc[nt][2] + bx, acc[nt][3] + by);
        v0.x = (v0.x > 0.0f) ? v0.x : 0.01f * v0.x;
        v0.y = (v0.y > 0.0f) ? v0.y : 0.01f * v0.y;
        v1.x = (v1.x > 0.0f) ? v1.x : 0.01f * v1.x;
        v1.y = (v1.y > 0.0f) ? v1.y : 0.01f * v1.y;
        if (row0 < N_NODES) *(float2*)(out + (size_t)row0 * F_OUT + col) = v0;
        if (row1 < N_NODES) *(float2*)(out + (size_t)row1 * F_OUT + col) = v1;
    }
}

// ---------------------------------------------------------------------------
// Harness entry. Inputs: h, pos, neighbor_idx, weight, bias_p
// ---------------------------------------------------------------------------
extern "C" void kernel_launch(void* const* d_in, const int* in_sizes, int n_in,
                              void* d_out, int out_size)
{
    const float* h    = (const float*)d_in[0];
    const float* pos  = (const float*)d_in[1];
    const int*   nidx = (const int*)d_in[2];
    const float* W    = (const float*)d_in[3];
    const float* bias = (const float*)d_in[4];
    float*       out  = (float*)d_out;

    static bool attr_set = false;
    if (!attr_set) {
        cudaFuncSetAttribute(gnn_mma_kernel,
                             cudaFuncAttributeMaxDynamicSharedMemorySize, SMEM_BYTES);
        attr_set = true;
    }

    convert_h_kernel<<<(N_NODES * F_IN / 8 + 255) / 256, 256>>>(h);
    frag_w_kernel<<<K_NBR, 256>>>(W);
    gnn_mma_kernel<<<NBLK, 256, SMEM_BYTES>>>(nidx, pos, bias, out);
}